// round 1
// baseline (speedup 1.0000x reference)
#include <cuda_runtime.h>

// ScalableCritic on GB300:
//   score[b] = lrelu(concat(gmax_b, cond_b) @ W3 + b3) @ W4 + b4
//   gmax_b   = segmented max over points of lrelu(lrelu([mu,cond]@W1+b1)@W2+b2)
//
// Kernel 1: per-batch lower_bound offsets (batch_index is sorted).
// Kernel 2: one block per batch, 128 threads; thread j owns output column j
//           with W2[:,j] in registers; fused decision MLP at block end.

#define TPB  128
#define TILE 32

__device__ int g_segoff[65537];   // supports B up to 65536

__global__ void segoff_kernel(const int* __restrict__ idx, int n, int B) {
    int b = blockIdx.x * blockDim.x + threadIdx.x;
    if (b > B) return;
    int lo = 0, hi = n;
    while (lo < hi) {                     // first i with idx[i] >= b
        int mid = (lo + hi) >> 1;
        if (idx[mid] < b) lo = mid + 1; else hi = mid;
    }
    g_segoff[b] = lo;
}

__device__ __forceinline__ float lrelu(float x) {
    // leaky_relu(x, 0.2) == max(x, 0.2x) exactly (0.2f < 1, monotone rounding)
    return fmaxf(x, 0.2f * x);
}

__global__ __launch_bounds__(TPB, 4)
void critic_kernel(const float* __restrict__ muons,
                   const float* __restrict__ cond,
                   const float* __restrict__ W1, const float* __restrict__ b1,
                   const float* __restrict__ W2, const float* __restrict__ b2,
                   const float* __restrict__ W3, const float* __restrict__ b3,
                   const float* __restrict__ W4, const float* __restrict__ b4,
                   float* __restrict__ out)
{
    const int b = blockIdx.x;
    const int j = threadIdx.x;            // 0..127: output column of layer 2

    __shared__ float sW1[192];            // W1 rows 0..2 (muon part), [f*64+k]
    __shared__ float scpre[64];           // b1 + cond_b @ W1[3:7]
    __shared__ float smu[TILE * 3];       // staged muons for current tile
    __shared__ float h1s[TILE * 64];      // layer-1 activations for tile
    __shared__ float din[132];            // decision input
    __shared__ float wsum[4];

    float c0 = cond[b * 4 + 0], c1 = cond[b * 4 + 1];
    float c2 = cond[b * 4 + 2], c3 = cond[b * 4 + 3];

    if (j < 64) {
        sW1[j]       = W1[0 * 64 + j];
        sW1[64 + j]  = W1[1 * 64 + j];
        sW1[128 + j] = W1[2 * 64 + j];
        float p = b1[j];
        p = fmaf(c0, W1[3 * 64 + j], p);
        p = fmaf(c1, W1[4 * 64 + j], p);
        p = fmaf(c2, W1[5 * 64 + j], p);
        p = fmaf(c3, W1[6 * 64 + j], p);
        scpre[j] = p;
    }

    // Thread j keeps W2[:, j] resident in registers (64 floats).
    float w2c[64];
#pragma unroll
    for (int k = 0; k < 64; k++) w2c[k] = W2[k * 128 + j];
    const float b2j = b2[j];

    __syncthreads();

    const int s = g_segoff[b];
    const int e = g_segoff[b + 1];
    float amax = -1.0e9f;                 // scatter-amax baseline

    for (int base = s; base < e; base += TILE) {
        const int cnt = min(TILE, e - base);

        // Stage muons for this tile (coalesced).
        if (j < cnt * 3) smu[j] = muons[base * 3 + j];
        __syncthreads();

        // Produce h1 tile: value (p,k) -> smem index p*64+k.
#pragma unroll
        for (int it = 0; it < (TILE * 64) / TPB; it++) {
            int v = j + it * TPB;
            int p = v >> 6, k = v & 63;
            if (p < cnt) {
                float x = scpre[k];
                x = fmaf(smu[p * 3 + 0], sW1[k],       x);
                x = fmaf(smu[p * 3 + 1], sW1[64 + k],  x);
                x = fmaf(smu[p * 3 + 2], sW1[128 + k], x);
                h1s[v] = lrelu(x);
            }
        }
        __syncthreads();

        // Consume: 64 FMA/point/thread, 4 independent accumulator chains.
        for (int p = 0; p < cnt; p++) {
            const float4* h4 = (const float4*)(h1s + p * 64);
            float s0 = b2j, s1 = 0.f, s2 = 0.f, s3 = 0.f;
#pragma unroll
            for (int q = 0; q < 16; q++) {
                float4 v = h4[q];
                s0 = fmaf(v.x, w2c[q * 4 + 0], s0);
                s1 = fmaf(v.y, w2c[q * 4 + 1], s1);
                s2 = fmaf(v.z, w2c[q * 4 + 2], s2);
                s3 = fmaf(v.w, w2c[q * 4 + 3], s3);
            }
            float h2 = lrelu((s0 + s1) + (s2 + s3));
            amax = fmaxf(amax, h2);
        }
        __syncthreads();
    }

    // Decision MLP: din = [gmax(128), cond(4)]
    din[j] = amax;
    if (j < 4) din[128 + j] = cond[b * 4 + j];
    __syncthreads();

    float acc = b3[j];
#pragma unroll 4
    for (int i = 0; i < 132; i++)
        acc = fmaf(din[i], W3[i * 128 + j], acc);
    float term = lrelu(acc) * W4[j];

#pragma unroll
    for (int o = 16; o > 0; o >>= 1)
        term += __shfl_down_sync(0xffffffffu, term, o);
    if ((j & 31) == 0) wsum[j >> 5] = term;
    __syncthreads();
    if (j == 0) out[b] = (wsum[0] + wsum[1]) + (wsum[2] + wsum[3]) + b4[0];
}

extern "C" void kernel_launch(void* const* d_in, const int* in_sizes, int n_in,
                              void* d_out, int out_size)
{
    const float* muons = (const float*)d_in[0];   // [N,3]
    const int*   bidx  = (const int*)  d_in[1];   // [N], sorted
    const float* cond  = (const float*)d_in[2];   // [B,4]

    // batch_size may or may not appear as a device input; disambiguate by size:
    // W1 has 7*64 = 448 elements, batch_size scalar has 1.
    int w = (n_in >= 12 && in_sizes[3] <= 2) ? 4 : 3;

    const float* W1 = (const float*)d_in[w + 0];
    const float* b1 = (const float*)d_in[w + 1];
    const float* W2 = (const float*)d_in[w + 2];
    const float* b2 = (const float*)d_in[w + 3];
    const float* W3 = (const float*)d_in[w + 4];
    const float* b3 = (const float*)d_in[w + 5];
    const float* W4 = (const float*)d_in[w + 6];
    const float* b4 = (const float*)d_in[w + 7];

    const int n = in_sizes[1];                    // N points
    const int B = out_size;                       // one score per batch

    segoff_kernel<<<(B + 1 + 255) / 256, 256>>>(bidx, n, B);
    critic_kernel<<<B, TPB>>>(muons, cond, W1, b1, W2, b2, W3, b3, W4, b4,
                              (float*)d_out);
}